// round 2
// baseline (speedup 1.0000x reference)
#include <cuda_runtime.h>
#include <cstdint>
#include <cstddef>

// Problem constants
#define NB   4
#define NTQ  256
#define NTK  256
#define ND   1024
#define NA   512

// Scratch for projections (allocation-free rule: __device__ globals)
__device__ float g_qp[NB * NTQ * NA];   // [b*TQ+q][a]
__device__ float g_kp[NB * NTK * NA];   // [b*TK+t][a]

// ---------------------------------------------------------------------------
// Projection GEMM: Y[m][n] = sum_d X[m][d] * W[n][d]
// M=1024 (b*TQ or b*TK), N=512 (a), D=1024. Both operands K-major (NT GEMM).
// 64x64 tile, BK=32, 256 threads, 4x4 per-thread register tile.
// blockIdx.z selects (Q,W1)->g_qp  or  (K,W2)->g_kp.
// ---------------------------------------------------------------------------
__global__ __launch_bounds__(256) void proj_kernel(
    const float* __restrict__ Qin, const float* __restrict__ Kin,
    const float* __restrict__ W1,  const float* __restrict__ W2)
{
    const float* X;
    const float* W;
    float* Y;
    if (blockIdx.z == 0) { X = Qin; W = W1; Y = g_qp; }
    else                 { X = Kin; W = W2; Y = g_kp; }

    // Transposed smem tiles As[k][m], Bs[k][n]; stride 68 floats (272B) keeps
    // float4 frag loads 16B-aligned and bank conflicts mild.
    __shared__ float As[32][68];
    __shared__ float Bs[32][68];

    const int tid = threadIdx.x;
    const int tx  = tid & 15;          // n-subtile
    const int ty  = tid >> 4;          // m-subtile
    const int m0  = blockIdx.y * 64;
    const int n0  = blockIdx.x * 64;

    float acc[4][4] = {};

    for (int k0 = 0; k0 < ND; k0 += 32) {
        // Cooperative load: 64 rows x 32 cols per operand, transposed store.
        const int r  = tid >> 3;          // 0..31
        const int c  = (tid & 7) * 4;     // 0..28
        #pragma unroll
        for (int i = 0; i < 2; i++) {
            const int rr = r + i * 32;
            float4 va = *(const float4*)(X + (size_t)(m0 + rr) * ND + k0 + c);
            As[c + 0][rr] = va.x; As[c + 1][rr] = va.y;
            As[c + 2][rr] = va.z; As[c + 3][rr] = va.w;
            float4 vb = *(const float4*)(W + (size_t)(n0 + rr) * ND + k0 + c);
            Bs[c + 0][rr] = vb.x; Bs[c + 1][rr] = vb.y;
            Bs[c + 2][rr] = vb.z; Bs[c + 3][rr] = vb.w;
        }
        __syncthreads();

        #pragma unroll
        for (int kk = 0; kk < 32; kk++) {
            float4 a = *(const float4*)&As[kk][ty * 4];
            float4 b = *(const float4*)&Bs[kk][tx * 4];
            float av[4] = {a.x, a.y, a.z, a.w};
            float bv[4] = {b.x, b.y, b.z, b.w};
            #pragma unroll
            for (int i = 0; i < 4; i++)
                #pragma unroll
                for (int j = 0; j < 4; j++)
                    acc[i][j] += av[i] * bv[j];
        }
        __syncthreads();
    }

    #pragma unroll
    for (int i = 0; i < 4; i++) {
        float4 o = make_float4(acc[i][0], acc[i][1], acc[i][2], acc[i][3]);
        *(float4*)(Y + (size_t)(m0 + ty * 4 + i) * NA + n0 + tx * 4) = o;
    }
}

// ---------------------------------------------------------------------------
// Fused score + masked softmax.
// CTA: one b, 4 consecutive q rows, all 256 t. 256 threads; thread == t.
// score[q][t] = sum_a w3[a] * tanh(qp[q][a] + kp[t][a]), A chunked by 32.
// kp staged TRANSPOSED in smem as kp_s[a][t] (stride 257 -> conflict-free
// both for the transposing stores and the per-a reads).
// mask is transported as int32 (bool promoted by the harness).
// ---------------------------------------------------------------------------
__global__ __launch_bounds__(256) void score_kernel(
    const int* __restrict__ mask, const float* __restrict__ w3,
    float* __restrict__ out)
{
    __shared__ float kp_s[32][257];
    __shared__ float qp_s[4][32];
    __shared__ float w3_s[NA];
    __shared__ float redm[4][8];
    __shared__ float reds[4][8];

    const int tid = threadIdx.x;            // == t
    const int b   = blockIdx.x >> 6;        // 64 q-tiles per b
    const int q0  = (blockIdx.x & 63) * 4;

    w3_s[tid]       = w3[tid];
    w3_s[tid + 256] = w3[tid + 256];

    const float* kpb = g_kp + (size_t)b * NTK * NA;
    const float* qpb = g_qp + ((size_t)b * NTQ + q0) * NA;

    float acc[4] = {0.f, 0.f, 0.f, 0.f};

    for (int ch = 0; ch < NA / 32; ch++) {
        const int a0 = ch * 32;
        __syncthreads();   // protect kp_s/qp_s from previous iteration readers
        {
            const int r  = tid >> 3;        // 0..31
            const int c4 = tid & 7;         // a-quad 0..7
            #pragma unroll
            for (int i = 0; i < 8; i++) {
                const int rr = r + i * 32;  // t row 0..255
                float4 v = *(const float4*)(kpb + (size_t)rr * NA + a0 + c4 * 4);
                kp_s[c4 * 4 + 0][rr] = v.x;
                kp_s[c4 * 4 + 1][rr] = v.y;
                kp_s[c4 * 4 + 2][rr] = v.z;
                kp_s[c4 * 4 + 3][rr] = v.w;
            }
            if (tid < 128) {
                const int qi = tid >> 5, aa = tid & 31;
                qp_s[qi][aa] = qpb[(size_t)qi * NA + a0 + aa];
            }
        }
        __syncthreads();

        #pragma unroll
        for (int a4 = 0; a4 < 8; a4++) {
            float4 wv = *(const float4*)&w3_s[a0 + a4 * 4];
            float kv0 = kp_s[a4 * 4 + 0][tid];
            float kv1 = kp_s[a4 * 4 + 1][tid];
            float kv2 = kp_s[a4 * 4 + 2][tid];
            float kv3 = kp_s[a4 * 4 + 3][tid];
            #pragma unroll
            for (int qi = 0; qi < 4; qi++) {
                float4 qv = *(const float4*)&qp_s[qi][a4 * 4];
                float t0, t1, t2, t3;
                asm("tanh.approx.f32 %0, %1;" : "=f"(t0) : "f"(qv.x + kv0));
                asm("tanh.approx.f32 %0, %1;" : "=f"(t1) : "f"(qv.y + kv1));
                asm("tanh.approx.f32 %0, %1;" : "=f"(t2) : "f"(qv.z + kv2));
                asm("tanh.approx.f32 %0, %1;" : "=f"(t3) : "f"(qv.w + kv3));
                acc[qi] += wv.x * t0 + wv.y * t1 + wv.z * t2 + wv.w * t3;
            }
        }
    }

    // Mask (int32 per element; nonzero == keep)
    const int* mrow = mask + ((size_t)b * NTQ + q0) * NTK + tid;
    float sc[4];
    #pragma unroll
    for (int qi = 0; qi < 4; qi++)
        sc[qi] = mrow[(size_t)qi * NTK] ? acc[qi] : -1e10f;

    const int lane = tid & 31, warp = tid >> 5;

    // Row max (warp reduce -> 8-warp combine in smem)
    #pragma unroll
    for (int qi = 0; qi < 4; qi++) {
        float v = sc[qi];
        #pragma unroll
        for (int o = 16; o; o >>= 1)
            v = fmaxf(v, __shfl_xor_sync(0xffffffffu, v, o));
        if (lane == 0) redm[qi][warp] = v;
    }
    __syncthreads();

    float ex[4];
    #pragma unroll
    for (int qi = 0; qi < 4; qi++) {
        float m = redm[qi][0];
        #pragma unroll
        for (int w = 1; w < 8; w++) m = fmaxf(m, redm[qi][w]);
        float e = exp2f((sc[qi] - m) * 1.4426950408889634f);
        ex[qi] = e;
        float v = e;
        #pragma unroll
        for (int o = 16; o; o >>= 1)
            v += __shfl_xor_sync(0xffffffffu, v, o);
        if (lane == 0) reds[qi][warp] = v;
    }
    __syncthreads();

    #pragma unroll
    for (int qi = 0; qi < 4; qi++) {
        float s = reds[qi][0];
        #pragma unroll
        for (int w = 1; w < 8; w++) s += reds[qi][w];
        out[((size_t)b * NTQ + q0 + qi) * NTK + tid] = ex[qi] * __frcp_rn(s);
    }
}

// ---------------------------------------------------------------------------
extern "C" void kernel_launch(void* const* d_in, const int* in_sizes, int n_in,
                              void* d_out, int out_size)
{
    const float* Q    = (const float*)d_in[0];
    const float* K    = (const float*)d_in[1];
    const int*   mask = (const int*)d_in[2];
    const float* W1   = (const float*)d_in[3];
    const float* W2   = (const float*)d_in[4];
    const float* w3   = (const float*)d_in[5];
    float*       out  = (float*)d_out;

    dim3 gp(NA / 64, (NB * NTQ) / 64, 2);   // 8 x 16 x 2 = 256 CTAs
    proj_kernel<<<gp, 256>>>(Q, K, W1, W2);

    score_kernel<<<NB * NTQ / 4, 256>>>(mask, w3, out);  // 256 CTAs
}

// round 4
// speedup vs baseline: 1.4458x; 1.4458x over previous
#include <cuda_runtime.h>
#include <cuda_bf16.h>
#include <cstdint>
#include <cstddef>

// Problem constants
#define NB   4
#define NTQ  256
#define NTK  256
#define ND   1024
#define NA   512

// Scratch (allocation-free rule: __device__ globals)
__device__ float g_qp [NB * NTQ * NA];    // [b*TQ+q][a]   row-major
__device__ float g_kpT[NA * NB * NTK];    // [a][b*TK+t]   TRANSPOSED

// ---------------------------------------------------------------------------
// Helpers
// ---------------------------------------------------------------------------
__device__ __forceinline__ uint32_t cvta_shared_u32(const void* p) {
    uint32_t a;
    asm("{ .reg .u64 t; cvta.to.shared.u64 t, %1; cvt.u32.u64 %0, t; }"
        : "=r"(a) : "l"(p));
    return a;
}

// Pack two floats into bf16x2 (a -> low 16 bits, b -> high).
__device__ __forceinline__ uint32_t pack_bf16x2(float a, float b) {
    uint32_t r;
    asm("cvt.rn.bf16x2.f32 %0, %1, %2;" : "=r"(r) : "f"(b), "f"(a));
    return r;
}

__device__ __forceinline__ void ldsm_x4(uint32_t* r, uint32_t addr) {
    asm volatile("ldmatrix.sync.aligned.m8n8.x4.shared.b16 {%0,%1,%2,%3}, [%4];"
                 : "=r"(r[0]), "=r"(r[1]), "=r"(r[2]), "=r"(r[3]) : "r"(addr));
}

__device__ __forceinline__ void mma_bf16(float* c, const uint32_t* a, const uint32_t* b) {
    asm volatile(
        "mma.sync.aligned.m16n8k16.row.col.f32.bf16.bf16.f32 "
        "{%0,%1,%2,%3}, {%4,%5,%6,%7}, {%8,%9}, {%0,%1,%2,%3};"
        : "+f"(c[0]), "+f"(c[1]), "+f"(c[2]), "+f"(c[3])
        : "r"(a[0]), "r"(a[1]), "r"(a[2]), "r"(a[3]), "r"(b[0]), "r"(b[1]));
}

// ---------------------------------------------------------------------------
// Tensor-core projection GEMM via mma.sync bf16 hi/lo split (3-MMA fp32 emu).
// Y[m][n] = sum_d X[m][d] * W[n][d];  M=1024 per z, N=512, K=1024.
// CTA tile 128(m) x 64(n), K-chunk 64, 8 warps (4m x 2n, 32x32 each).
// z=0: Q*W1 -> g_qp (row-major).  z=1: K*W2 -> g_kpT (transposed [a][m]).
// ---------------------------------------------------------------------------
#define BM 128
#define BN 64
#define BK 64
#define RS 72                    // smem row stride in bf16 (144 B)
#define A_TILE_B  (BM * RS * 2)  // 18432
#define B_TILE_B  (BN * RS * 2)  //  9216
#define STAGE_B   (2 * A_TILE_B + 2 * B_TILE_B)   // Ah, Al, Bh, Bl = 55296
#define OFF_AH 0
#define OFF_AL A_TILE_B
#define OFF_BH (2 * A_TILE_B)
#define OFF_BL (2 * A_TILE_B + B_TILE_B)
#define SMEM_DYN (2 * STAGE_B)   // 110592

extern __shared__ char dynsmem[];

__global__ __launch_bounds__(256, 1) void proj_tc_kernel(
    const float* __restrict__ Qin, const float* __restrict__ Kin,
    const float* __restrict__ W1,  const float* __restrict__ W2)
{
    const int z  = blockIdx.z;
    const float* X = z ? Kin : Qin;
    const float* W = z ? W2  : W1;
    const int m0 = blockIdx.y * BM;
    const int n0 = blockIdx.x * BN;

    const int tid  = threadIdx.x;
    const int wid  = tid >> 5;
    const int lane = tid & 31;
    const int wm   = wid >> 1;        // 0..3
    const int wn   = wid & 1;         // 0..1

    const uint32_t sbase = cvta_shared_u32(dynsmem);

    // ldmatrix per-lane row/k offsets (bf16 element units)
    const int a_row = (lane & 7) + ((lane >> 3) & 1) * 8;   // 0..15
    const int a_kof = (lane >> 4) * 8;                      // 0 / 8
    const int b_row = (lane & 7) + ((lane >> 4) & 1) * 8;
    const int b_kof = ((lane >> 3) & 1) * 8;

    float acc[2][4][4] = {};   // [mi][nf][4]

    float4 va[8], vb[4];

    // global load of chunk ch into registers
    auto load_regs = [&](int ch) {
        const int k0 = ch * BK;
        #pragma unroll
        for (int i = 0; i < 8; i++) {
            const int idx = tid + i * 256;          // 0..2047
            const int row = idx >> 4;               // 0..127
            const int c4  = (idx & 15) * 4;
            va[i] = *(const float4*)(X + (size_t)(m0 + row) * ND + k0 + c4);
        }
        #pragma unroll
        for (int i = 0; i < 4; i++) {
            const int idx = tid + i * 256;          // 0..1023
            const int row = idx >> 4;               // 0..63
            const int c4  = (idx & 15) * 4;
            vb[i] = *(const float4*)(W + (size_t)(n0 + row) * ND + k0 + c4);
        }
    };

    // convert + store registers into smem stage s
    auto store_smem = [&](int s) {
        char* st = dynsmem + s * STAGE_B;
        #pragma unroll
        for (int i = 0; i < 8; i++) {
            const int idx = tid + i * 256;
            const int row = idx >> 4;
            const int c4  = idx & 15;
            const uint32_t off = (uint32_t)(row * (RS * 2) + c4 * 8);
            uint32_t h01 = pack_bf16x2(va[i].x, va[i].y);
            uint32_t h23 = pack_bf16x2(va[i].z, va[i].w);
            float lx = va[i].x - __uint_as_float(h01 << 16);
            float ly = va[i].y - __uint_as_float(h01 & 0xffff0000u);
            float lz = va[i].z - __uint_as_float(h23 << 16);
            float lw = va[i].w - __uint_as_float(h23 & 0xffff0000u);
            *(uint2*)(st + OFF_AH + off) = make_uint2(h01, h23);
            *(uint2*)(st + OFF_AL + off) = make_uint2(pack_bf16x2(lx, ly), pack_bf16x2(lz, lw));
        }
        #pragma unroll
        for (int i = 0; i < 4; i++) {
            const int idx = tid + i * 256;
            const int row = idx >> 4;
            const int c4  = idx & 15;
            const uint32_t off = (uint32_t)(row * (RS * 2) + c4 * 8);
            uint32_t h01 = pack_bf16x2(vb[i].x, vb[i].y);
            uint32_t h23 = pack_bf16x2(vb[i].z, vb[i].w);
            float lx = vb[i].x - __uint_as_float(h01 << 16);
            float ly = vb[i].y - __uint_as_float(h01 & 0xffff0000u);
            float lz = vb[i].z - __uint_as_float(h23 << 16);
            float lw = vb[i].w - __uint_as_float(h23 & 0xffff0000u);
            *(uint2*)(st + OFF_BH + off) = make_uint2(h01, h23);
            *(uint2*)(st + OFF_BL + off) = make_uint2(pack_bf16x2(lx, ly), pack_bf16x2(lz, lw));
        }
    };

    auto compute = [&](int s) {
        const uint32_t st = sbase + (uint32_t)(s * STAGE_B);
        #pragma unroll
        for (int ks = 0; ks < 4; ks++) {
            const uint32_t kb = (uint32_t)(ks * 16 * 2);
            uint32_t ah[2][4], al[2][4], bh[4][2], bl[4][2];
            #pragma unroll
            for (int mi = 0; mi < 2; mi++) {
                const uint32_t ra = st + (uint32_t)((wm * 32 + mi * 16 + a_row) * (RS * 2))
                                   + kb + (uint32_t)(a_kof * 2);
                ldsm_x4(ah[mi], ra + OFF_AH);
                ldsm_x4(al[mi], ra + OFF_AL);
            }
            #pragma unroll
            for (int bi = 0; bi < 2; bi++) {
                const uint32_t rb = st + (uint32_t)((wn * 32 + bi * 16 + b_row) * (RS * 2))
                                   + kb + (uint32_t)(b_kof * 2);
                uint32_t t0[4], t1[4];
                ldsm_x4(t0, rb + OFF_BH);
                ldsm_x4(t1, rb + OFF_BL);
                bh[bi*2+0][0] = t0[0]; bh[bi*2+0][1] = t0[1];
                bh[bi*2+1][0] = t0[2]; bh[bi*2+1][1] = t0[3];
                bl[bi*2+0][0] = t1[0]; bl[bi*2+0][1] = t1[1];
                bl[bi*2+1][0] = t1[2]; bl[bi*2+1][1] = t1[3];
            }
            #pragma unroll
            for (int mi = 0; mi < 2; mi++)
                #pragma unroll
                for (int nf = 0; nf < 4; nf++) {
                    mma_bf16(acc[mi][nf], ah[mi], bh[nf]);
                    mma_bf16(acc[mi][nf], ah[mi], bl[nf]);
                    mma_bf16(acc[mi][nf], al[mi], bh[nf]);
                }
        }
    };

    load_regs(0);
    store_smem(0);
    __syncthreads();

    for (int ch = 0; ch < 16; ch++) {
        const int s = ch & 1;
        if (ch < 15) load_regs(ch + 1);
        compute(s);
        if (ch < 15) store_smem(s ^ 1);
        __syncthreads();
    }

    // -------- Epilogue: stage 128x64 fp32 tile in smem (stride 65) --------
    float* ep = (float*)dynsmem;   // 128 * 65 * 4 = 33280 B
    #pragma unroll
    for (int mi = 0; mi < 2; mi++)
        #pragma unroll
        for (int nf = 0; nf < 4; nf++)
            #pragma unroll
            for (int j = 0; j < 4; j++) {
                const int r = wm * 32 + mi * 16 + (lane >> 2) + (j >> 1) * 8;
                const int c = wn * 32 + nf * 8 + (lane & 3) * 2 + (j & 1);
                ep[r * 65 + c] = acc[mi][nf][j];
            }
    __syncthreads();

    if (z == 0) {
        #pragma unroll
        for (int i = 0; i < 8; i++) {
            const int idx = tid + i * 256;
            const int row = idx >> 4;
            const int c4  = (idx & 15) * 4;
            float4 v = make_float4(ep[row * 65 + c4 + 0], ep[row * 65 + c4 + 1],
                                   ep[row * 65 + c4 + 2], ep[row * 65 + c4 + 3]);
            *(float4*)(g_qp + (size_t)(m0 + row) * NA + n0 + c4) = v;
        }
    } else {
        #pragma unroll
        for (int i = 0; i < 32; i++) {
            const int idx = tid + i * 256;    // 0..8191
            const int c   = idx >> 7;         // 0..63
            const int m   = idx & 127;        // 0..127
            g_kpT[(size_t)(n0 + c) * (NB * NTK) + m0 + m] = ep[m * 65 + c];
        }
    }
}

// ---------------------------------------------------------------------------
// Fused score + masked softmax. CTA = (b, 4 q rows), 256 threads, thread == t.
// kp read directly from transposed g_kpT (coalesced LDG, L2-resident) — no
// in-loop __syncthreads, warps free-run into the MUFU pipe.
// ---------------------------------------------------------------------------
__global__ __launch_bounds__(256) void score_kernel(
    const int* __restrict__ mask, const float* __restrict__ w3,
    float* __restrict__ out)
{
    __shared__ float qp_s[4 * NA];
    __shared__ float w3_s[NA];
    __shared__ float redm[4][8];
    __shared__ float reds[4][8];

    const int tid = threadIdx.x;            // == t
    const int b   = blockIdx.x >> 6;
    const int q0  = (blockIdx.x & 63) * 4;

    w3_s[tid]       = w3[tid];
    w3_s[tid + 256] = w3[tid + 256];
    {
        const float* qpb = g_qp + ((size_t)b * NTQ + q0) * NA;  // 4 contiguous rows
        #pragma unroll
        for (int i = 0; i < 8; i++) qp_s[tid + i * 256] = qpb[tid + i * 256];
    }
    __syncthreads();

    const float* kcol = g_kpT + (size_t)b * NTK + tid;   // + a * 1024

    float acc[4] = {0.f, 0.f, 0.f, 0.f};

    for (int a0 = 0; a0 < NA; a0 += 8) {
        float kv[8];
        #pragma unroll
        for (int j = 0; j < 8; j++) kv[j] = __ldg(kcol + (size_t)(a0 + j) * (NB * NTK));
        #pragma unroll
        for (int j = 0; j < 8; j++) {
            const float w = w3_s[a0 + j];
            #pragma unroll
            for (int q = 0; q < 4; q++) {
                float t;
                asm("tanh.approx.f32 %0, %1;" : "=f"(t) : "f"(qp_s[q * NA + a0 + j] + kv[j]));
                acc[q] = fmaf(w, t, acc[q]);
            }
        }
    }

    // Mask (int32; nonzero == keep)
    const int* mrow = mask + ((size_t)b * NTQ + q0) * NTK + tid;
    float sc[4];
    #pragma unroll
    for (int q = 0; q < 4; q++)
        sc[q] = mrow[(size_t)q * NTK] ? acc[q] : -1e10f;

    const int lane = tid & 31, warp = tid >> 5;

    #pragma unroll
    for (int q = 0; q < 4; q++) {
        float v = sc[q];
        #pragma unroll
        for (int o = 16; o; o >>= 1) v = fmaxf(v, __shfl_xor_sync(0xffffffffu, v, o));
        if (lane == 0) redm[q][warp] = v;
    }
    __syncthreads();

    float ex[4];
    #pragma unroll
    for (int q = 0; q < 4; q++) {
        float m = redm[q][0];
        #pragma unroll
        for (int w = 1; w < 8; w++) m = fmaxf(m, redm[q][w]);
        float e = exp2f((sc[q] - m) * 1.4426950408889634f);
        ex[q] = e;
        float v = e;
        #pragma unroll
        for (int o = 16; o; o >>= 1) v += __shfl_xor_sync(0xffffffffu, v, o);
        if (lane == 0) reds[q][warp] = v;
    }
    __syncthreads();

    #pragma unroll
    for (int q = 0; q < 4; q++) {
        float s = reds[q][0];
        #pragma unroll
        for (int w = 1; w < 8; w++) s += reds[q][w];
        out[((size_t)b * NTQ + q0 + q) * NTK + tid] = ex[q] * __frcp_rn(s);
    }
}

// ---------------------------------------------------------------------------
extern "C" void kernel_launch(void* const* d_in, const int* in_sizes, int n_in,
                              void* d_out, int out_size)
{
    const float* Q    = (const float*)d_in[0];
    const float* K    = (const float*)d_in[1];
    const int*   mask = (const int*)d_in[2];
    const float* W1   = (const float*)d_in[3];
    const float* W2   = (const float*)d_in[4];
    const float* w3   = (const float*)d_in[5];
    float*       out  = (float*)d_out;

    cudaFuncSetAttribute(proj_tc_kernel,
                         cudaFuncAttributeMaxDynamicSharedMemorySize, SMEM_DYN);

    dim3 gp(NA / BN, (NB * NTQ) / BM, 2);   // 8 x 8 x 2 = 128 CTAs
    proj_tc_kernel<<<gp, 256, SMEM_DYN>>>(Q, K, W1, W2);

    score_kernel<<<NB * NTQ / 4, 256>>>(mask, w3, out);   // 256 CTAs
}

// round 5
// speedup vs baseline: 1.9133x; 1.3234x over previous
#include <cuda_runtime.h>
#include <cuda_bf16.h>
#include <cstdint>
#include <cstddef>

// Problem constants
#define NB   4
#define NTQ  256
#define NTK  256
#define ND   1024
#define NA   512

// Scratch (allocation-free rule: __device__ globals)
__device__ float g_qp [NB * NTQ * NA];    // [b*TQ+q][a]   row-major
__device__ float g_kpT[NA * NB * NTK];    // [a][b*TK+t]   TRANSPOSED

// ---------------------------------------------------------------------------
// Helpers
// ---------------------------------------------------------------------------
__device__ __forceinline__ uint32_t cvta_shared_u32(const void* p) {
    uint32_t a;
    asm("{ .reg .u64 t; cvta.to.shared.u64 t, %1; cvt.u32.u64 %0, t; }"
        : "=r"(a) : "l"(p));
    return a;
}

// Pack two floats into bf16x2 (a -> low 16 bits, b -> high).
__device__ __forceinline__ uint32_t pack_bf16x2(float a, float b) {
    uint32_t r;
    asm("cvt.rn.bf16x2.f32 %0, %1, %2;" : "=r"(r) : "f"(b), "f"(a));
    return r;
}

__device__ __forceinline__ void ldsm_x4(uint32_t* r, uint32_t addr) {
    asm volatile("ldmatrix.sync.aligned.m8n8.x4.shared.b16 {%0,%1,%2,%3}, [%4];"
                 : "=r"(r[0]), "=r"(r[1]), "=r"(r[2]), "=r"(r[3]) : "r"(addr));
}

__device__ __forceinline__ void mma_bf16(float* c, const uint32_t* a, const uint32_t* b) {
    asm volatile(
        "mma.sync.aligned.m16n8k16.row.col.f32.bf16.bf16.f32 "
        "{%0,%1,%2,%3}, {%4,%5,%6,%7}, {%8,%9}, {%0,%1,%2,%3};"
        : "+f"(c[0]), "+f"(c[1]), "+f"(c[2]), "+f"(c[3])
        : "r"(a[0]), "r"(a[1]), "r"(a[2]), "r"(a[3]), "r"(b[0]), "r"(b[1]));
}

// ---------------------------------------------------------------------------
// Tensor-core projection GEMM via mma.sync bf16 hi/lo split (3-MMA fp32 emu).
// Y[m][n] = sum_d X[m][d] * W[n][d];  M=1024 per z, N=512, K=1024.
// CTA tile 128(m) x 64(n), K-chunk 64, 8 warps (4m x 2n, 32x32 each).
// z=0: Q*W1 -> g_qp (row-major).  z=1: K*W2 -> g_kpT (transposed [a][m]).
// ---------------------------------------------------------------------------
#define BM 128
#define BN 64
#define BK 64
#define RS 72                    // smem row stride in bf16 (144 B)
#define A_TILE_B  (BM * RS * 2)  // 18432
#define B_TILE_B  (BN * RS * 2)  //  9216
#define STAGE_B   (2 * A_TILE_B + 2 * B_TILE_B)   // Ah, Al, Bh, Bl = 55296
#define OFF_AH 0
#define OFF_AL A_TILE_B
#define OFF_BH (2 * A_TILE_B)
#define OFF_BL (2 * A_TILE_B + B_TILE_B)
#define SMEM_DYN (2 * STAGE_B)   // 110592

extern __shared__ char dynsmem[];

__global__ __launch_bounds__(256, 1) void proj_tc_kernel(
    const float* __restrict__ Qin, const float* __restrict__ Kin,
    const float* __restrict__ W1,  const float* __restrict__ W2)
{
    const int z  = blockIdx.z;
    const float* X = z ? Kin : Qin;
    const float* W = z ? W2  : W1;
    const int m0 = blockIdx.y * BM;
    const int n0 = blockIdx.x * BN;

    const int tid  = threadIdx.x;
    const int wid  = tid >> 5;
    const int lane = tid & 31;
    const int wm   = wid >> 1;        // 0..3
    const int wn   = wid & 1;         // 0..1

    const uint32_t sbase = cvta_shared_u32(dynsmem);

    const int a_row = (lane & 7) + ((lane >> 3) & 1) * 8;   // 0..15
    const int a_kof = (lane >> 4) * 8;                      // 0 / 8
    const int b_row = (lane & 7) + ((lane >> 4) & 1) * 8;
    const int b_kof = ((lane >> 3) & 1) * 8;

    float acc[2][4][4] = {};   // [mi][nf][4]

    float4 va[8], vb[4];

    auto load_regs = [&](int ch) {
        const int k0 = ch * BK;
        #pragma unroll
        for (int i = 0; i < 8; i++) {
            const int idx = tid + i * 256;
            const int row = idx >> 4;
            const int c4  = (idx & 15) * 4;
            va[i] = *(const float4*)(X + (size_t)(m0 + row) * ND + k0 + c4);
        }
        #pragma unroll
        for (int i = 0; i < 4; i++) {
            const int idx = tid + i * 256;
            const int row = idx >> 4;
            const int c4  = (idx & 15) * 4;
            vb[i] = *(const float4*)(W + (size_t)(n0 + row) * ND + k0 + c4);
        }
    };

    auto store_smem = [&](int s) {
        char* st = dynsmem + s * STAGE_B;
        #pragma unroll
        for (int i = 0; i < 8; i++) {
            const int idx = tid + i * 256;
            const int row = idx >> 4;
            const int c4  = idx & 15;
            const uint32_t off = (uint32_t)(row * (RS * 2) + c4 * 8);
            uint32_t h01 = pack_bf16x2(va[i].x, va[i].y);
            uint32_t h23 = pack_bf16x2(va[i].z, va[i].w);
            float lx = va[i].x - __uint_as_float(h01 << 16);
            float ly = va[i].y - __uint_as_float(h01 & 0xffff0000u);
            float lz = va[i].z - __uint_as_float(h23 << 16);
            float lw = va[i].w - __uint_as_float(h23 & 0xffff0000u);
            *(uint2*)(st + OFF_AH + off) = make_uint2(h01, h23);
            *(uint2*)(st + OFF_AL + off) = make_uint2(pack_bf16x2(lx, ly), pack_bf16x2(lz, lw));
        }
        #pragma unroll
        for (int i = 0; i < 4; i++) {
            const int idx = tid + i * 256;
            const int row = idx >> 4;
            const int c4  = idx & 15;
            const uint32_t off = (uint32_t)(row * (RS * 2) + c4 * 8);
            uint32_t h01 = pack_bf16x2(vb[i].x, vb[i].y);
            uint32_t h23 = pack_bf16x2(vb[i].z, vb[i].w);
            float lx = vb[i].x - __uint_as_float(h01 << 16);
            float ly = vb[i].y - __uint_as_float(h01 & 0xffff0000u);
            float lz = vb[i].z - __uint_as_float(h23 << 16);
            float lw = vb[i].w - __uint_as_float(h23 & 0xffff0000u);
            *(uint2*)(st + OFF_BH + off) = make_uint2(h01, h23);
            *(uint2*)(st + OFF_BL + off) = make_uint2(pack_bf16x2(lx, ly), pack_bf16x2(lz, lw));
        }
    };

    auto compute = [&](int s) {
        const uint32_t st = sbase + (uint32_t)(s * STAGE_B);
        #pragma unroll
        for (int ks = 0; ks < 4; ks++) {
            const uint32_t kb = (uint32_t)(ks * 16 * 2);
            uint32_t ah[2][4], al[2][4], bh[4][2], bl[4][2];
            #pragma unroll
            for (int mi = 0; mi < 2; mi++) {
                const uint32_t ra = st + (uint32_t)((wm * 32 + mi * 16 + a_row) * (RS * 2))
                                   + kb + (uint32_t)(a_kof * 2);
                ldsm_x4(ah[mi], ra + OFF_AH);
                ldsm_x4(al[mi], ra + OFF_AL);
            }
            #pragma unroll
            for (int bi = 0; bi < 2; bi++) {
                const uint32_t rb = st + (uint32_t)((wn * 32 + bi * 16 + b_row) * (RS * 2))
                                   + kb + (uint32_t)(b_kof * 2);
                uint32_t t0[4], t1[4];
                ldsm_x4(t0, rb + OFF_BH);
                ldsm_x4(t1, rb + OFF_BL);
                bh[bi*2+0][0] = t0[0]; bh[bi*2+0][1] = t0[1];
                bh[bi*2+1][0] = t0[2]; bh[bi*2+1][1] = t0[3];
                bl[bi*2+0][0] = t1[0]; bl[bi*2+0][1] = t1[1];
                bl[bi*2+1][0] = t1[2]; bl[bi*2+1][1] = t1[3];
            }
            #pragma unroll
            for (int mi = 0; mi < 2; mi++)
                #pragma unroll
                for (int nf = 0; nf < 4; nf++) {
                    mma_bf16(acc[mi][nf], ah[mi], bh[nf]);
                    mma_bf16(acc[mi][nf], ah[mi], bl[nf]);
                    mma_bf16(acc[mi][nf], al[mi], bh[nf]);
                }
        }
    };

    load_regs(0);
    store_smem(0);
    __syncthreads();

    for (int ch = 0; ch < 16; ch++) {
        const int s = ch & 1;
        if (ch < 15) load_regs(ch + 1);
        compute(s);
        if (ch < 15) store_smem(s ^ 1);
        __syncthreads();
    }

    // -------- Epilogue: stage 128x64 fp32 tile in smem (stride 65) --------
    float* ep = (float*)dynsmem;
    #pragma unroll
    for (int mi = 0; mi < 2; mi++)
        #pragma unroll
        for (int nf = 0; nf < 4; nf++)
            #pragma unroll
            for (int j = 0; j < 4; j++) {
                const int r = wm * 32 + mi * 16 + (lane >> 2) + (j >> 1) * 8;
                const int c = wn * 32 + nf * 8 + (lane & 3) * 2 + (j & 1);
                ep[r * 65 + c] = acc[mi][nf][j];
            }
    __syncthreads();

    if (z == 0) {
        #pragma unroll
        for (int i = 0; i < 8; i++) {
            const int idx = tid + i * 256;
            const int row = idx >> 4;
            const int c4  = (idx & 15) * 4;
            float4 v = make_float4(ep[row * 65 + c4 + 0], ep[row * 65 + c4 + 1],
                                   ep[row * 65 + c4 + 2], ep[row * 65 + c4 + 3]);
            *(float4*)(g_qp + (size_t)(m0 + row) * NA + n0 + c4) = v;
        }
    } else {
        #pragma unroll
        for (int i = 0; i < 32; i++) {
            const int idx = tid + i * 256;
            const int c   = idx >> 7;
            const int m   = idx & 127;
            g_kpT[(size_t)(n0 + c) * (NB * NTK) + m0 + m] = ep[m * 65 + c];
        }
    }
}

// ---------------------------------------------------------------------------
// Fused score + masked softmax, v3.
// CTA = (b, 4 q rows), 512 threads = 2 a-halves x 256 t. Grid 256 CTAs.
// Each a-half sums its 256 a's; halves combine through smem; softmax on the
// low 256 threads. kv loads double-buffered in registers for latency hiding.
// ---------------------------------------------------------------------------
__global__ __launch_bounds__(512, 2) void score_kernel(
    const int* __restrict__ mask, const float* __restrict__ w3,
    float* __restrict__ out)
{
    __shared__ float qp_s[4][NA];
    __shared__ float w3_s[NA];
    __shared__ float part[4][NTK];
    __shared__ float redm[4][8];
    __shared__ float reds[4][8];

    const int tid = threadIdx.x;
    const int t   = tid & 255;              // key index
    const int ah  = tid >> 8;               // a-half 0/1
    const int b   = blockIdx.x >> 6;
    const int q0  = (blockIdx.x & 63) * 4;

    w3_s[tid] = w3[tid];                    // 512 threads -> full w3
    {
        const float* qpb = g_qp + ((size_t)b * NTQ + q0) * NA;  // 4 contiguous rows
        #pragma unroll
        for (int i = 0; i < 4; i++) qp_s[0][tid + i * 512] = qpb[tid + i * 512];
    }
    __syncthreads();

    const int aBeg = ah * 256;
    const float* kcol = g_kpT + (size_t)aBeg * (NB * NTK) + (size_t)b * NTK + t;

    float acc[4] = {0.f, 0.f, 0.f, 0.f};

    // register double-buffered kv prefetch (8 a per step, 32 steps)
    float kv[8], kvn[8];
    #pragma unroll
    for (int j = 0; j < 8; j++)
        kv[j] = __ldg(kcol + (size_t)j * (NB * NTK));

    for (int it = 0; it < 32; it++) {
        const int a0 = aBeg + it * 8;
        if (it < 31) {
            const float* kn = kcol + (size_t)((it + 1) * 8) * (NB * NTK);
            #pragma unroll
            for (int j = 0; j < 8; j++)
                kvn[j] = __ldg(kn + (size_t)j * (NB * NTK));
        }
        #pragma unroll
        for (int j4 = 0; j4 < 2; j4++) {
            float4 wv = *(const float4*)&w3_s[a0 + j4 * 4];
            float4 q0v = *(const float4*)&qp_s[0][a0 + j4 * 4];
            float4 q1v = *(const float4*)&qp_s[1][a0 + j4 * 4];
            float4 q2v = *(const float4*)&qp_s[2][a0 + j4 * 4];
            float4 q3v = *(const float4*)&qp_s[3][a0 + j4 * 4];
            const float* kj = &kv[j4 * 4];
            #pragma unroll
            for (int e = 0; e < 4; e++) {
                const float kk = kj[e];
                const float w  = (&wv.x)[e];
                float t0, t1, t2, t3;
                asm("tanh.approx.f32 %0, %1;" : "=f"(t0) : "f"((&q0v.x)[e] + kk));
                asm("tanh.approx.f32 %0, %1;" : "=f"(t1) : "f"((&q1v.x)[e] + kk));
                asm("tanh.approx.f32 %0, %1;" : "=f"(t2) : "f"((&q2v.x)[e] + kk));
                asm("tanh.approx.f32 %0, %1;" : "=f"(t3) : "f"((&q3v.x)[e] + kk));
                acc[0] = fmaf(w, t0, acc[0]);
                acc[1] = fmaf(w, t1, acc[1]);
                acc[2] = fmaf(w, t2, acc[2]);
                acc[3] = fmaf(w, t3, acc[3]);
            }
        }
        #pragma unroll
        for (int j = 0; j < 8; j++) kv[j] = kvn[j];
    }

    // combine a-halves
    if (ah == 1) {
        #pragma unroll
        for (int q = 0; q < 4; q++) part[q][t] = acc[q];
    }
    __syncthreads();

    if (ah == 0) {
        #pragma unroll
        for (int q = 0; q < 4; q++) acc[q] += part[q][t];

        // Mask (int32; nonzero == keep)
        const int* mrow = mask + ((size_t)b * NTQ + q0) * NTK + t;
        float sc[4];
        #pragma unroll
        for (int q = 0; q < 4; q++)
            sc[q] = mrow[(size_t)q * NTK] ? acc[q] : -1e10f;

        const int lane = t & 31, warp = t >> 5;

        #pragma unroll
        for (int q = 0; q < 4; q++) {
            float v = sc[q];
            #pragma unroll
            for (int o = 16; o; o >>= 1) v = fmaxf(v, __shfl_xor_sync(0xffffffffu, v, o));
            if (lane == 0) redm[q][warp] = v;
        }
        __syncthreads();

        float ex[4];
        #pragma unroll
        for (int q = 0; q < 4; q++) {
            float m = redm[q][0];
            #pragma unroll
            for (int w = 1; w < 8; w++) m = fmaxf(m, redm[q][w]);
            float e = exp2f((sc[q] - m) * 1.4426950408889634f);
            ex[q] = e;
            float v = e;
            #pragma unroll
            for (int o = 16; o; o >>= 1) v += __shfl_xor_sync(0xffffffffu, v, o);
            if (lane == 0) reds[q][warp] = v;
        }
        __syncthreads();

        #pragma unroll
        for (int q = 0; q < 4; q++) {
            float s = reds[q][0];
            #pragma unroll
            for (int w = 1; w < 8; w++) s += reds[q][w];
            out[((size_t)b * NTQ + q0 + q) * NTK + t] = ex[q] * __frcp_rn(s);
        }
    } else {
        // keep barrier counts matched for the two softmax __syncthreads
        __syncthreads();
        __syncthreads();
    }
}

// ---------------------------------------------------------------------------
extern "C" void kernel_launch(void* const* d_in, const int* in_sizes, int n_in,
                              void* d_out, int out_size)
{
    const float* Q    = (const float*)d_in[0];
    const float* K    = (const float*)d_in[1];
    const int*   mask = (const int*)d_in[2];
    const float* W1   = (const float*)d_in[3];
    const float* W2   = (const float*)d_in[4];
    const float* w3   = (const float*)d_in[5];
    float*       out  = (float*)d_out;

    cudaFuncSetAttribute(proj_tc_kernel,
                         cudaFuncAttributeMaxDynamicSharedMemorySize, SMEM_DYN);

    dim3 gp(NA / BN, (NB * NTQ) / BM, 2);   // 8 x 8 x 2 = 128 CTAs
    proj_tc_kernel<<<gp, 256, SMEM_DYN>>>(Q, K, W1, W2);

    score_kernel<<<NB * NTQ / 4, 512>>>(mask, w3, out);   // 256 CTAs
}